// round 15
// baseline (speedup 1.0000x reference)
#include <cuda_runtime.h>
#include <cuda_fp16.h>
#include <cstdint>

// LNN Euler-Lagrange residual: ReLU MLP => grad-of-grad vanishes under
// autodiff; output is exactly -dL/dq.
//
// R15: heterogeneous persistent kernel.
//  - 296 HMMA CTAs (2/SM): R14 mma.sync chain (240 MMAs / 16-row tile,
//    sitting exactly on the measured 16-cyc/mma sequencer roofline).
//  - 148 SIMT CTAs (1/SM): scalar fp32 path for a static 12.5% sample
//    tail, weights read via __constant__ (LDC port, not the L1/LDS
//    crossbar the HMMA path uses). W2^T (the one transposed view) staged
//    in the SIMT CTA's own smem.
// Static split keeps determinism (both paths' rounding is fixed per sample).

typedef uint32_t u32;
typedef unsigned long long u64;

#define INV2048 4.8828125e-4f
#define NH    296
#define NSIMT 148
#define GRID  (NH + NSIMT)

__constant__ float cW1[4096];
__constant__ float cW2[4096];
__constant__ float cb1[64];
__constant__ float cb2[64];
__constant__ float cW3[64];

__device__ __forceinline__ u32 smem_addr(const void* p) {
    u32 a;
    asm("{ .reg .u64 t; cvta.to.shared.u64 t, %1; cvt.u32.u64 %0, t; }"
        : "=r"(a) : "l"(p));
    return a;
}
__device__ __forceinline__ u32 pack_f16x2(float x0, float x1) {   // lo=x0, hi=x1
    u32 r; asm("cvt.rn.f16x2.f32 %0, %1, %2;" : "=r"(r) : "f"(x1), "f"(x0));
    return r;
}
__device__ __forceinline__ float2 unpack_h2(u32 v) {
    float2 r;
    asm("{ .reg .b16 lo1, hi1; mov.b32 {lo1, hi1}, %2; "
        "cvt.f32.f16 %0, lo1; cvt.f32.f16 %1, hi1; }"
        : "=f"(r.x), "=f"(r.y) : "r"(v));
    return r;
}
__device__ __forceinline__ void split2s(float x0, float x1, u32& hi, u32& lo) {
    hi = pack_f16x2(x0, x1);
    const float2 hf = unpack_h2(hi);
    lo = pack_f16x2((x0 - hf.x) * 2048.0f, (x1 - hf.y) * 2048.0f);
}
__device__ __forceinline__ void ldm4(u32 r[4], u32 addr) {
    asm volatile("ldmatrix.sync.aligned.m8n8.x4.shared.b16 {%0,%1,%2,%3}, [%4];"
                 : "=r"(r[0]), "=r"(r[1]), "=r"(r[2]), "=r"(r[3]) : "r"(addr));
}
#define MMA(cc, aa, b0, b1)                                                  \
    asm volatile("mma.sync.aligned.m16n8k16.row.col.f32.f16.f16.f32 "        \
        "{%0,%1,%2,%3}, {%4,%5,%6,%7}, {%8,%9}, {%0,%1,%2,%3};"              \
        : "+f"((cc)[0]), "+f"((cc)[1]), "+f"((cc)[2]), "+f"((cc)[3])         \
        : "r"((aa)[0]), "r"((aa)[1]), "r"((aa)[2]), "r"((aa)[3]),            \
          "r"(b0), "r"(b1))
#define MMAH(hh, aa, b0, b1)                                                 \
    asm volatile("mma.sync.aligned.m16n8k16.row.col.f16.f16.f16.f16 "        \
        "{%0,%1}, {%2,%3,%4,%5}, {%6,%7}, {%0,%1};"                          \
        : "+r"((hh)[0]), "+r"((hh)[1])                                       \
        : "r"((aa)[0]), "r"((aa)[1]), "r"((aa)[2]), "r"((aa)[3]),            \
          "r"(b0), "r"(b1))

// HMMA smem layout (weight tiles [n][k] fp16, stride 72 halfs).
#define OB_W1T_H 0
#define OB_W1T_L 9216
#define OB_W2T_H 18432
#define OB_W2T_L 27648
#define OB_V_H   36864
#define OB_W1Q_H 46080
#define OB_B1    50688
#define OB_B2    50944
#define SMEM_TOTAL 51200

#define G_CHUNK3(c, Ah, Al, BH, BL, nt) do {                                 \
    u32 b0h[4], b0l[4], b1h[4], b1l[4];                                      \
    ldm4(b0h, (BH) + (nt) * 1152);                                           \
    ldm4(b0l, (BL) + (nt) * 1152);                                           \
    ldm4(b1h, (BH) + (nt) * 1152 + 64);                                      \
    ldm4(b1l, (BL) + (nt) * 1152 + 64);                                      \
    float* cA = (c)[nt];                                                     \
    cA[0] = 0.f; cA[1] = 0.f; cA[2] = 0.f; cA[3] = 0.f;                      \
    u32 rh[2]; rh[0] = 0u; rh[1] = 0u;                                       \
    MMA(cA, (Ah)[0], b0h[0], b0h[1]);                                        \
    MMAH(rh, (Ah)[0], b0l[0], b0l[1]);                                       \
    MMAH(rh, (Al)[0], b0h[0], b0h[1]);                                       \
    MMA(cA, (Ah)[1], b0h[2], b0h[3]);                                        \
    MMAH(rh, (Ah)[1], b0l[2], b0l[3]);                                       \
    MMAH(rh, (Al)[1], b0h[2], b0h[3]);                                       \
    MMA(cA, (Ah)[2], b1h[0], b1h[1]);                                        \
    MMAH(rh, (Ah)[2], b1l[0], b1l[1]);                                       \
    MMAH(rh, (Al)[2], b1h[0], b1h[1]);                                       \
    MMA(cA, (Ah)[3], b1h[2], b1h[3]);                                        \
    MMAH(rh, (Ah)[3], b1l[2], b1l[3]);                                       \
    MMAH(rh, (Al)[3], b1h[2], b1h[3]);                                       \
    const float2 u0 = unpack_h2(rh[0]);                                      \
    const float2 u1 = unpack_h2(rh[1]);                                      \
    cA[0] = fmaf(u0.x, INV2048, cA[0]);                                      \
    cA[1] = fmaf(u0.y, INV2048, cA[1]);                                      \
    cA[2] = fmaf(u1.x, INV2048, cA[2]);                                      \
    cA[3] = fmaf(u1.y, INV2048, cA[3]);                                      \
} while (0)

#define G_CHUNK1(c, Ah, BH, nt) do {                                         \
    u32 b0h[4], b1h[4];                                                      \
    ldm4(b0h, (BH) + (nt) * 1152);                                           \
    ldm4(b1h, (BH) + (nt) * 1152 + 64);                                      \
    float* cA = (c)[nt];                                                     \
    cA[0] = 0.f; cA[1] = 0.f; cA[2] = 0.f; cA[3] = 0.f;                      \
    MMA(cA, (Ah)[0], b0h[0], b0h[1]);                                        \
    MMA(cA, (Ah)[1], b0h[2], b0h[3]);                                        \
    MMA(cA, (Ah)[2], b1h[0], b1h[1]);                                        \
    MMA(cA, (Ah)[3], b1h[2], b1h[3]);                                        \
} while (0)

// SIMT helper: accumulate h[64] += xi * (weight row), row via float4 ptr.
#define SL1_ACC(XI, ROWP) do {                                               \
    const float4* _w = (ROWP);                                               \
    _Pragma("unroll")                                                        \
    for (int j4 = 0; j4 < 16; j4++) {                                        \
        float4 w = _w[j4];                                                   \
        h[4*j4+0] = fmaf((XI), w.x, h[4*j4+0]);                              \
        h[4*j4+1] = fmaf((XI), w.y, h[4*j4+1]);                              \
        h[4*j4+2] = fmaf((XI), w.z, h[4*j4+2]);                              \
        h[4*j4+3] = fmaf((XI), w.w, h[4*j4+3]);                              \
    }                                                                        \
} while (0)

__global__ void __launch_bounds__(128, 3)
lnn_kernel(const float* __restrict__ X,
           const float* __restrict__ W1g, const float* __restrict__ b1g,
           const float* __restrict__ W2g, const float* __restrict__ b2g,
           const float* __restrict__ W3g,
           float* __restrict__ out, int B)
{
    extern __shared__ char smem[];
    const int tid = threadIdx.x;
    const int bx = blockIdx.x;

    // Static split: SIMT handles the last NS samples (multiple of 64).
    int NS = (B >= 65536) ? ((B >> 3) & ~63) : 0;
    const int B0 = B - NS;

    if (bx < NH) {
        // ===================== HMMA path (R14) =====================
        __half* sh = reinterpret_cast<__half*>(smem);
        float* sb1 = reinterpret_cast<float*>(smem + OB_B1);
        float* sb2 = reinterpret_cast<float*>(smem + OB_B2);
        const int wid = tid >> 5, lane = tid & 31;
        const int g = lane >> 2, tig = lane & 3;

        for (int idx = tid; idx < 4096; idx += 128) {
            const int r = idx >> 6, cc = idx & 63;
            {
                const float v = W1g[idx];
                const __half hh = __float2half_rn(v);
                const __half hl = __float2half_rn((v - __half2float(hh)) * 2048.0f);
                sh[(OB_W1T_H >> 1) + cc * 72 + r] = hh;
                sh[(OB_W1T_L >> 1) + cc * 72 + r] = hl;
                if (r < 32)
                    sh[(OB_W1Q_H >> 1) + r * 72 + cc] = hh;
            }
            {
                const float v = W2g[idx];
                const __half hh = __float2half_rn(v);
                const __half hl = __float2half_rn((v - __half2float(hh)) * 2048.0f);
                sh[(OB_W2T_H >> 1) + cc * 72 + r] = hh;
                sh[(OB_W2T_L >> 1) + cc * 72 + r] = hl;
                const float vv = v * W3g[cc];
                sh[(OB_V_H >> 1) + r * 72 + cc] = __float2half_rn(vv);
            }
        }
        if (tid < 64) { sb1[tid] = b1g[tid]; sb2[tid] = b2g[tid]; }
        __syncthreads();

        const u32 sbase = smem_addr(smem);
        const u32 laneoff = (lane & 7) * 144 + (lane >> 3) * 16;
        const u32 bW1T_h = sbase + OB_W1T_H + laneoff, bW1T_l = sbase + OB_W1T_L + laneoff;
        const u32 bW2T_h = sbase + OB_W2T_H + laneoff, bW2T_l = sbase + OB_W2T_L + laneoff;
        const u32 bV_h   = sbase + OB_V_H   + laneoff;
        const u32 bW1Q_h = sbase + OB_W1Q_H + laneoff;

        const int ntiles = (B0 + 63) >> 6;
        float c[8][4];
        u32 Ah[4][4], Al[4][4];

        for (int tile = bx; tile < ntiles; tile += NH) {
            const int rowbase = tile * 64 + wid * 16;
            {
                int r0 = rowbase + g;
                int r1 = r0 + 8;
                if (r0 >= B0) r0 = B0 - 1;
                if (r1 >= B0) r1 = B0 - 1;
                const float* x0 = X + (size_t)r0 * 64 + 2 * tig;
                const float* x1 = X + (size_t)r1 * 64 + 2 * tig;
                #pragma unroll
                for (int kt = 0; kt < 4; kt++) {
                    const float2 v00 = *reinterpret_cast<const float2*>(x0 + 16*kt);
                    const float2 v01 = *reinterpret_cast<const float2*>(x0 + 16*kt + 8);
                    const float2 v10 = *reinterpret_cast<const float2*>(x1 + 16*kt);
                    const float2 v11 = *reinterpret_cast<const float2*>(x1 + 16*kt + 8);
                    split2s(v00.x, v00.y, Ah[kt][0], Al[kt][0]);
                    split2s(v10.x, v10.y, Ah[kt][1], Al[kt][1]);
                    split2s(v01.x, v01.y, Ah[kt][2], Al[kt][2]);
                    split2s(v11.x, v11.y, Ah[kt][3], Al[kt][3]);
                }
            }

            // GEMM1
            #pragma unroll
            for (int nt = 0; nt < 8; nt++)
                G_CHUNK3(c, Ah, Al, bW1T_h, bW1T_l, nt);
            u32 m1 = 0u;
            #pragma unroll
            for (int nt = 0; nt < 8; nt++) {
                const float2 bv = *reinterpret_cast<const float2*>(sb1 + 8*nt + 2*tig);
                float p0 = c[nt][0] + bv.x;
                float p1 = c[nt][1] + bv.y;
                float p2 = c[nt][2] + bv.x;
                float p3 = c[nt][3] + bv.y;
                if (p0 > 0.0f) m1 |= 1u << (4*nt + 0); else p0 = 0.0f;
                if (p1 > 0.0f) m1 |= 1u << (4*nt + 1); else p1 = 0.0f;
                if (p2 > 0.0f) m1 |= 1u << (4*nt + 2); else p2 = 0.0f;
                if (p3 > 0.0f) m1 |= 1u << (4*nt + 3); else p3 = 0.0f;
                const int kt = nt >> 1, o = (nt & 1) << 1;
                split2s(p0, p1, Ah[kt][o],     Al[kt][o]);
                split2s(p2, p3, Ah[kt][o + 1], Al[kt][o + 1]);
            }

            // GEMM2
            #pragma unroll
            for (int nt = 0; nt < 8; nt++)
                G_CHUNK3(c, Ah, Al, bW2T_h, bW2T_l, nt);
            #pragma unroll
            for (int nt = 0; nt < 8; nt++) {
                const float2 bv = *reinterpret_cast<const float2*>(sb2 + 8*nt + 2*tig);
                const float d0 = (c[nt][0] + bv.x > 0.0f) ? 1.0f : 0.0f;
                const float d1 = (c[nt][1] + bv.y > 0.0f) ? 1.0f : 0.0f;
                const float d2 = (c[nt][2] + bv.x > 0.0f) ? 1.0f : 0.0f;
                const float d3 = (c[nt][3] + bv.y > 0.0f) ? 1.0f : 0.0f;
                const int kt = nt >> 1, o = (nt & 1) << 1;
                Ah[kt][o]     = pack_f16x2(d0, d1);
                Ah[kt][o + 1] = pack_f16x2(d2, d3);
            }

            // GEMM3 (1-product)
            #pragma unroll
            for (int nt = 0; nt < 8; nt++)
                G_CHUNK1(c, Ah, bV_h, nt);
            #pragma unroll
            for (int nt = 0; nt < 8; nt++) {
                const float t0 = ((m1 >> (4*nt + 0)) & 1u) ? -c[nt][0] : 0.0f;
                const float t1 = ((m1 >> (4*nt + 1)) & 1u) ? -c[nt][1] : 0.0f;
                const float t2 = ((m1 >> (4*nt + 2)) & 1u) ? -c[nt][2] : 0.0f;
                const float t3 = ((m1 >> (4*nt + 3)) & 1u) ? -c[nt][3] : 0.0f;
                const int kt = nt >> 1, o = (nt & 1) << 1;
                Ah[kt][o]     = pack_f16x2(t0, t1);
                Ah[kt][o + 1] = pack_f16x2(t2, t3);
            }

            // GEMM4 (1-product)
            #pragma unroll
            for (int nt = 0; nt < 4; nt++)
                G_CHUNK1(c, Ah, bW1Q_h, nt);
            {
                const int r0 = rowbase + g;
                const int r1 = r0 + 8;
                #pragma unroll
                for (int nt = 0; nt < 4; nt++) {
                    const int col = 8 * nt + 2 * tig;
                    if (r0 < B0)
                        *reinterpret_cast<float2*>(out + (size_t)r0 * 32 + col) =
                            make_float2(c[nt][0], c[nt][1]);
                    if (r1 < B0)
                        *reinterpret_cast<float2*>(out + (size_t)r1 * 32 + col) =
                            make_float2(c[nt][2], c[nt][3]);
                }
            }
        }
    } else {
        // ===================== SIMT path (fp32, constant-mem weights) ======
        float* sW2T = reinterpret_cast<float*>(smem);   // 16 KB: W2^T rows
        for (int i = tid; i < 4096; i += 128) {
            const int r = i >> 6, cc = i & 63;
            sW2T[cc * 64 + r] = W2g[i];                 // row cc = W2[:,cc]
        }
        __syncthreads();
        if (NS == 0) return;

        const int bx2 = bx - NH;
        for (int s = B0 + bx2 * 128 + tid; s < B; s += NSIMT * 128) {
            float h[64];
            #pragma unroll
            for (int j = 0; j < 64; j++) h[j] = cb1[j];

            const float4* xg = reinterpret_cast<const float4*>(X + (size_t)s * 64);
            #pragma unroll 1
            for (int i4 = 0; i4 < 16; i4++) {
                const float4 xv = xg[i4];
                const float4* row = reinterpret_cast<const float4*>(cW1 + i4 * 256);
                SL1_ACC(xv.x, row);
                SL1_ACC(xv.y, row + 16);
                SL1_ACC(xv.z, row + 32);
                SL1_ACC(xv.w, row + 48);
            }

            u64 m1 = 0ull;
            #pragma unroll
            for (int j = 0; j < 64; j++) {
                h[j] = fmaxf(h[j], 0.0f);
                if (h[j] > 0.0f) m1 |= 1ull << j;
            }

            // sign(h @ W2 + b2) via W2^T rows from smem
            u64 m2 = 0ull;
            #pragma unroll 2
            for (int j = 0; j < 64; j++) {
                const float4* wp = reinterpret_cast<const float4*>(sW2T + j * 64);
                float s0 = 0.f, s1 = 0.f, s2 = 0.f, s3 = 0.f;
                #pragma unroll
                for (int e = 0; e < 16; e++) {
                    float4 w = wp[e];
                    s0 = fmaf(w.x, h[4*e+0], s0);
                    s1 = fmaf(w.y, h[4*e+1], s1);
                    s2 = fmaf(w.z, h[4*e+2], s2);
                    s3 = fmaf(w.w, h[4*e+3], s3);
                }
                if (((s0 + s1) + (s2 + s3)) + cb2[j] > 0.0f) m2 |= 1ull << j;
            }

            // d2 into h (h dead)
            #pragma unroll
            for (int j = 0; j < 64; j++)
                h[j] = ((m2 >> j) & 1ull) ? cW3[j] : 0.0f;

            // d1_k = mask1_k * -(W2[k,:] . d2)
            float d1[64];
            #pragma unroll
            for (int k = 0; k < 64; k++) {
                const float4* wp = reinterpret_cast<const float4*>(cW2 + k * 64);
                float s0 = 0.f, s1 = 0.f, s2 = 0.f, s3 = 0.f;
                #pragma unroll
                for (int e = 0; e < 16; e++) {
                    float4 w = wp[e];
                    s0 = fmaf(w.x, h[4*e+0], s0);
                    s1 = fmaf(w.y, h[4*e+1], s1);
                    s2 = fmaf(w.z, h[4*e+2], s2);
                    s3 = fmaf(w.w, h[4*e+3], s3);
                }
                const float dk = (s0 + s1) + (s2 + s3);
                d1[k] = ((m1 >> k) & 1ull) ? -dk : 0.0f;
            }

            // out_i = W1[i,:] . d1 (negation folded above), i < 32
            float* og = out + (size_t)s * 32;
            #pragma unroll 1
            for (int i4 = 0; i4 < 8; i4++) {
                float acc[4];
                #pragma unroll
                for (int u = 0; u < 4; u++) {
                    const int i = 4 * i4 + u;
                    const float4* wp = reinterpret_cast<const float4*>(cW1 + i * 64);
                    float s0 = 0.f, s1 = 0.f, s2 = 0.f, s3 = 0.f;
                    #pragma unroll
                    for (int e = 0; e < 16; e++) {
                        float4 w = wp[e];
                        s0 = fmaf(w.x, d1[4*e+0], s0);
                        s1 = fmaf(w.y, d1[4*e+1], s1);
                        s2 = fmaf(w.z, d1[4*e+2], s2);
                        s3 = fmaf(w.w, d1[4*e+3], s3);
                    }
                    acc[u] = (s0 + s1) + (s2 + s3);
                }
                float4 r;
                r.x = acc[0]; r.y = acc[1]; r.z = acc[2]; r.w = acc[3];
                reinterpret_cast<float4*>(og)[i4] = r;
            }
        }
    }
}

extern "C" void kernel_launch(void* const* d_in, const int* in_sizes, int n_in,
                              void* d_out, int out_size)
{
    const float* X  = (const float*)d_in[0];
    const float* W1 = (const float*)d_in[1];
    const float* b1 = (const float*)d_in[2];
    const float* W2 = (const float*)d_in[3];
    const float* b2 = (const float*)d_in[4];
    const float* W3 = (const float*)d_in[5];
    float* out = (float*)d_out;

    const int B = in_sizes[0] / 64;

    cudaMemcpyToSymbolAsync(cW1, W1, 4096 * sizeof(float), 0,
                            cudaMemcpyDeviceToDevice, 0);
    cudaMemcpyToSymbolAsync(cW2, W2, 4096 * sizeof(float), 0,
                            cudaMemcpyDeviceToDevice, 0);
    cudaMemcpyToSymbolAsync(cb1, b1, 64 * sizeof(float), 0,
                            cudaMemcpyDeviceToDevice, 0);
    cudaMemcpyToSymbolAsync(cb2, b2, 64 * sizeof(float), 0,
                            cudaMemcpyDeviceToDevice, 0);
    cudaMemcpyToSymbolAsync(cW3, W3, 64 * sizeof(float), 0,
                            cudaMemcpyDeviceToDevice, 0);

    cudaFuncSetAttribute(lnn_kernel,
                         cudaFuncAttributeMaxDynamicSharedMemorySize,
                         SMEM_TOTAL);
    lnn_kernel<<<GRID, 128, SMEM_TOTAL>>>(X, W1, b1, W2, b2, W3, out, B);
}

// round 16
// speedup vs baseline: 1.0182x; 1.0182x over previous
#include <cuda_runtime.h>
#include <cuda_fp16.h>
#include <cstdint>

// LNN Euler-Lagrange residual: ReLU MLP => grad-of-grad vanishes under
// autodiff; output is exactly -dL/dq.
//
// R15: heterogeneous persistent kernel.
//  - 296 HMMA CTAs (2/SM): R14 mma.sync chain (240 MMAs / 16-row tile,
//    sitting exactly on the measured 16-cyc/mma sequencer roofline).
//  - 148 SIMT CTAs (1/SM): scalar fp32 path for a static 12.5% sample
//    tail, weights read via __constant__ (LDC port, not the L1/LDS
//    crossbar the HMMA path uses). W2^T (the one transposed view) staged
//    in the SIMT CTA's own smem.
// Static split keeps determinism (both paths' rounding is fixed per sample).

typedef uint32_t u32;
typedef unsigned long long u64;

#define INV2048 4.8828125e-4f
#define NH    296
#define NSIMT 148
#define GRID  (NH + NSIMT)

__constant__ float cW1[4096];
__constant__ float cW2[4096];
__constant__ float cb1[64];
__constant__ float cb2[64];
__constant__ float cW3[64];

__device__ __forceinline__ u32 smem_addr(const void* p) {
    u32 a;
    asm("{ .reg .u64 t; cvta.to.shared.u64 t, %1; cvt.u32.u64 %0, t; }"
        : "=r"(a) : "l"(p));
    return a;
}
__device__ __forceinline__ u32 pack_f16x2(float x0, float x1) {   // lo=x0, hi=x1
    u32 r; asm("cvt.rn.f16x2.f32 %0, %1, %2;" : "=r"(r) : "f"(x1), "f"(x0));
    return r;
}
__device__ __forceinline__ float2 unpack_h2(u32 v) {
    float2 r;
    asm("{ .reg .b16 lo1, hi1; mov.b32 {lo1, hi1}, %2; "
        "cvt.f32.f16 %0, lo1; cvt.f32.f16 %1, hi1; }"
        : "=f"(r.x), "=f"(r.y) : "r"(v));
    return r;
}
__device__ __forceinline__ void split2s(float x0, float x1, u32& hi, u32& lo) {
    hi = pack_f16x2(x0, x1);
    const float2 hf = unpack_h2(hi);
    lo = pack_f16x2((x0 - hf.x) * 2048.0f, (x1 - hf.y) * 2048.0f);
}
__device__ __forceinline__ void ldm4(u32 r[4], u32 addr) {
    asm volatile("ldmatrix.sync.aligned.m8n8.x4.shared.b16 {%0,%1,%2,%3}, [%4];"
                 : "=r"(r[0]), "=r"(r[1]), "=r"(r[2]), "=r"(r[3]) : "r"(addr));
}
#define MMA(cc, aa, b0, b1)                                                  \
    asm volatile("mma.sync.aligned.m16n8k16.row.col.f32.f16.f16.f32 "        \
        "{%0,%1,%2,%3}, {%4,%5,%6,%7}, {%8,%9}, {%0,%1,%2,%3};"              \
        : "+f"((cc)[0]), "+f"((cc)[1]), "+f"((cc)[2]), "+f"((cc)[3])         \
        : "r"((aa)[0]), "r"((aa)[1]), "r"((aa)[2]), "r"((aa)[3]),            \
          "r"(b0), "r"(b1))
#define MMAH(hh, aa, b0, b1)                                                 \
    asm volatile("mma.sync.aligned.m16n8k16.row.col.f16.f16.f16.f16 "        \
        "{%0,%1}, {%2,%3,%4,%5}, {%6,%7}, {%0,%1};"                          \
        : "+r"((hh)[0]), "+r"((hh)[1])                                       \
        : "r"((aa)[0]), "r"((aa)[1]), "r"((aa)[2]), "r"((aa)[3]),            \
          "r"(b0), "r"(b1))

// HMMA smem layout (weight tiles [n][k] fp16, stride 72 halfs).
#define OB_W1T_H 0
#define OB_W1T_L 9216
#define OB_W2T_H 18432
#define OB_W2T_L 27648
#define OB_V_H   36864
#define OB_W1Q_H 46080
#define OB_B1    50688
#define OB_B2    50944
#define SMEM_TOTAL 51200

#define G_CHUNK3(c, Ah, Al, BH, BL, nt) do {                                 \
    u32 b0h[4], b0l[4], b1h[4], b1l[4];                                      \
    ldm4(b0h, (BH) + (nt) * 1152);                                           \
    ldm4(b0l, (BL) + (nt) * 1152);                                           \
    ldm4(b1h, (BH) + (nt) * 1152 + 64);                                      \
    ldm4(b1l, (BL) + (nt) * 1152 + 64);                                      \
    float* cA = (c)[nt];                                                     \
    cA[0] = 0.f; cA[1] = 0.f; cA[2] = 0.f; cA[3] = 0.f;                      \
    u32 rh[2]; rh[0] = 0u; rh[1] = 0u;                                       \
    MMA(cA, (Ah)[0], b0h[0], b0h[1]);                                        \
    MMAH(rh, (Ah)[0], b0l[0], b0l[1]);                                       \
    MMAH(rh, (Al)[0], b0h[0], b0h[1]);                                       \
    MMA(cA, (Ah)[1], b0h[2], b0h[3]);                                        \
    MMAH(rh, (Ah)[1], b0l[2], b0l[3]);                                       \
    MMAH(rh, (Al)[1], b0h[2], b0h[3]);                                       \
    MMA(cA, (Ah)[2], b1h[0], b1h[1]);                                        \
    MMAH(rh, (Ah)[2], b1l[0], b1l[1]);                                       \
    MMAH(rh, (Al)[2], b1h[0], b1h[1]);                                       \
    MMA(cA, (Ah)[3], b1h[2], b1h[3]);                                        \
    MMAH(rh, (Ah)[3], b1l[2], b1l[3]);                                       \
    MMAH(rh, (Al)[3], b1h[2], b1h[3]);                                       \
    const float2 u0 = unpack_h2(rh[0]);                                      \
    const float2 u1 = unpack_h2(rh[1]);                                      \
    cA[0] = fmaf(u0.x, INV2048, cA[0]);                                      \
    cA[1] = fmaf(u0.y, INV2048, cA[1]);                                      \
    cA[2] = fmaf(u1.x, INV2048, cA[2]);                                      \
    cA[3] = fmaf(u1.y, INV2048, cA[3]);                                      \
} while (0)

#define G_CHUNK1(c, Ah, BH, nt) do {                                         \
    u32 b0h[4], b1h[4];                                                      \
    ldm4(b0h, (BH) + (nt) * 1152);                                           \
    ldm4(b1h, (BH) + (nt) * 1152 + 64);                                      \
    float* cA = (c)[nt];                                                     \
    cA[0] = 0.f; cA[1] = 0.f; cA[2] = 0.f; cA[3] = 0.f;                      \
    MMA(cA, (Ah)[0], b0h[0], b0h[1]);                                        \
    MMA(cA, (Ah)[1], b0h[2], b0h[3]);                                        \
    MMA(cA, (Ah)[2], b1h[0], b1h[1]);                                        \
    MMA(cA, (Ah)[3], b1h[2], b1h[3]);                                        \
} while (0)

// SIMT helper: accumulate h[64] += xi * (weight row), row via float4 ptr.
#define SL1_ACC(XI, ROWP) do {                                               \
    const float4* _w = (ROWP);                                               \
    _Pragma("unroll")                                                        \
    for (int j4 = 0; j4 < 16; j4++) {                                        \
        float4 w = _w[j4];                                                   \
        h[4*j4+0] = fmaf((XI), w.x, h[4*j4+0]);                              \
        h[4*j4+1] = fmaf((XI), w.y, h[4*j4+1]);                              \
        h[4*j4+2] = fmaf((XI), w.z, h[4*j4+2]);                              \
        h[4*j4+3] = fmaf((XI), w.w, h[4*j4+3]);                              \
    }                                                                        \
} while (0)

__global__ void __launch_bounds__(128, 3)
lnn_kernel(const float* __restrict__ X,
           const float* __restrict__ W1g, const float* __restrict__ b1g,
           const float* __restrict__ W2g, const float* __restrict__ b2g,
           const float* __restrict__ W3g,
           float* __restrict__ out, int B)
{
    extern __shared__ char smem[];
    const int tid = threadIdx.x;
    const int bx = blockIdx.x;

    // Static split: SIMT handles the last NS samples (multiple of 64).
    int NS = (B >= 65536) ? ((B >> 3) & ~63) : 0;
    const int B0 = B - NS;

    if (bx < NH) {
        // ===================== HMMA path (R14) =====================
        __half* sh = reinterpret_cast<__half*>(smem);
        float* sb1 = reinterpret_cast<float*>(smem + OB_B1);
        float* sb2 = reinterpret_cast<float*>(smem + OB_B2);
        const int wid = tid >> 5, lane = tid & 31;
        const int g = lane >> 2, tig = lane & 3;

        for (int idx = tid; idx < 4096; idx += 128) {
            const int r = idx >> 6, cc = idx & 63;
            {
                const float v = W1g[idx];
                const __half hh = __float2half_rn(v);
                const __half hl = __float2half_rn((v - __half2float(hh)) * 2048.0f);
                sh[(OB_W1T_H >> 1) + cc * 72 + r] = hh;
                sh[(OB_W1T_L >> 1) + cc * 72 + r] = hl;
                if (r < 32)
                    sh[(OB_W1Q_H >> 1) + r * 72 + cc] = hh;
            }
            {
                const float v = W2g[idx];
                const __half hh = __float2half_rn(v);
                const __half hl = __float2half_rn((v - __half2float(hh)) * 2048.0f);
                sh[(OB_W2T_H >> 1) + cc * 72 + r] = hh;
                sh[(OB_W2T_L >> 1) + cc * 72 + r] = hl;
                const float vv = v * W3g[cc];
                sh[(OB_V_H >> 1) + r * 72 + cc] = __float2half_rn(vv);
            }
        }
        if (tid < 64) { sb1[tid] = b1g[tid]; sb2[tid] = b2g[tid]; }
        __syncthreads();

        const u32 sbase = smem_addr(smem);
        const u32 laneoff = (lane & 7) * 144 + (lane >> 3) * 16;
        const u32 bW1T_h = sbase + OB_W1T_H + laneoff, bW1T_l = sbase + OB_W1T_L + laneoff;
        const u32 bW2T_h = sbase + OB_W2T_H + laneoff, bW2T_l = sbase + OB_W2T_L + laneoff;
        const u32 bV_h   = sbase + OB_V_H   + laneoff;
        const u32 bW1Q_h = sbase + OB_W1Q_H + laneoff;

        const int ntiles = (B0 + 63) >> 6;
        float c[8][4];
        u32 Ah[4][4], Al[4][4];

        for (int tile = bx; tile < ntiles; tile += NH) {
            const int rowbase = tile * 64 + wid * 16;
            {
                int r0 = rowbase + g;
                int r1 = r0 + 8;
                if (r0 >= B0) r0 = B0 - 1;
                if (r1 >= B0) r1 = B0 - 1;
                const float* x0 = X + (size_t)r0 * 64 + 2 * tig;
                const float* x1 = X + (size_t)r1 * 64 + 2 * tig;
                #pragma unroll
                for (int kt = 0; kt < 4; kt++) {
                    const float2 v00 = *reinterpret_cast<const float2*>(x0 + 16*kt);
                    const float2 v01 = *reinterpret_cast<const float2*>(x0 + 16*kt + 8);
                    const float2 v10 = *reinterpret_cast<const float2*>(x1 + 16*kt);
                    const float2 v11 = *reinterpret_cast<const float2*>(x1 + 16*kt + 8);
                    split2s(v00.x, v00.y, Ah[kt][0], Al[kt][0]);
                    split2s(v10.x, v10.y, Ah[kt][1], Al[kt][1]);
                    split2s(v01.x, v01.y, Ah[kt][2], Al[kt][2]);
                    split2s(v11.x, v11.y, Ah[kt][3], Al[kt][3]);
                }
            }

            // GEMM1
            #pragma unroll
            for (int nt = 0; nt < 8; nt++)
                G_CHUNK3(c, Ah, Al, bW1T_h, bW1T_l, nt);
            u32 m1 = 0u;
            #pragma unroll
            for (int nt = 0; nt < 8; nt++) {
                const float2 bv = *reinterpret_cast<const float2*>(sb1 + 8*nt + 2*tig);
                float p0 = c[nt][0] + bv.x;
                float p1 = c[nt][1] + bv.y;
                float p2 = c[nt][2] + bv.x;
                float p3 = c[nt][3] + bv.y;
                if (p0 > 0.0f) m1 |= 1u << (4*nt + 0); else p0 = 0.0f;
                if (p1 > 0.0f) m1 |= 1u << (4*nt + 1); else p1 = 0.0f;
                if (p2 > 0.0f) m1 |= 1u << (4*nt + 2); else p2 = 0.0f;
                if (p3 > 0.0f) m1 |= 1u << (4*nt + 3); else p3 = 0.0f;
                const int kt = nt >> 1, o = (nt & 1) << 1;
                split2s(p0, p1, Ah[kt][o],     Al[kt][o]);
                split2s(p2, p3, Ah[kt][o + 1], Al[kt][o + 1]);
            }

            // GEMM2
            #pragma unroll
            for (int nt = 0; nt < 8; nt++)
                G_CHUNK3(c, Ah, Al, bW2T_h, bW2T_l, nt);
            #pragma unroll
            for (int nt = 0; nt < 8; nt++) {
                const float2 bv = *reinterpret_cast<const float2*>(sb2 + 8*nt + 2*tig);
                const float d0 = (c[nt][0] + bv.x > 0.0f) ? 1.0f : 0.0f;
                const float d1 = (c[nt][1] + bv.y > 0.0f) ? 1.0f : 0.0f;
                const float d2 = (c[nt][2] + bv.x > 0.0f) ? 1.0f : 0.0f;
                const float d3 = (c[nt][3] + bv.y > 0.0f) ? 1.0f : 0.0f;
                const int kt = nt >> 1, o = (nt & 1) << 1;
                Ah[kt][o]     = pack_f16x2(d0, d1);
                Ah[kt][o + 1] = pack_f16x2(d2, d3);
            }

            // GEMM3 (1-product)
            #pragma unroll
            for (int nt = 0; nt < 8; nt++)
                G_CHUNK1(c, Ah, bV_h, nt);
            #pragma unroll
            for (int nt = 0; nt < 8; nt++) {
                const float t0 = ((m1 >> (4*nt + 0)) & 1u) ? -c[nt][0] : 0.0f;
                const float t1 = ((m1 >> (4*nt + 1)) & 1u) ? -c[nt][1] : 0.0f;
                const float t2 = ((m1 >> (4*nt + 2)) & 1u) ? -c[nt][2] : 0.0f;
                const float t3 = ((m1 >> (4*nt + 3)) & 1u) ? -c[nt][3] : 0.0f;
                const int kt = nt >> 1, o = (nt & 1) << 1;
                Ah[kt][o]     = pack_f16x2(t0, t1);
                Ah[kt][o + 1] = pack_f16x2(t2, t3);
            }

            // GEMM4 (1-product)
            #pragma unroll
            for (int nt = 0; nt < 4; nt++)
                G_CHUNK1(c, Ah, bW1Q_h, nt);
            {
                const int r0 = rowbase + g;
                const int r1 = r0 + 8;
                #pragma unroll
                for (int nt = 0; nt < 4; nt++) {
                    const int col = 8 * nt + 2 * tig;
                    if (r0 < B0)
                        *reinterpret_cast<float2*>(out + (size_t)r0 * 32 + col) =
                            make_float2(c[nt][0], c[nt][1]);
                    if (r1 < B0)
                        *reinterpret_cast<float2*>(out + (size_t)r1 * 32 + col) =
                            make_float2(c[nt][2], c[nt][3]);
                }
            }
        }
    } else {
        // ===================== SIMT path (fp32, constant-mem weights) ======
        float* sW2T = reinterpret_cast<float*>(smem);   // 16 KB: W2^T rows
        for (int i = tid; i < 4096; i += 128) {
            const int r = i >> 6, cc = i & 63;
            sW2T[cc * 64 + r] = W2g[i];                 // row cc = W2[:,cc]
        }
        __syncthreads();
        if (NS == 0) return;

        const int bx2 = bx - NH;
        for (int s = B0 + bx2 * 128 + tid; s < B; s += NSIMT * 128) {
            float h[64];
            #pragma unroll
            for (int j = 0; j < 64; j++) h[j] = cb1[j];

            const float4* xg = reinterpret_cast<const float4*>(X + (size_t)s * 64);
            #pragma unroll 1
            for (int i4 = 0; i4 < 16; i4++) {
                const float4 xv = xg[i4];
                const float4* row = reinterpret_cast<const float4*>(cW1 + i4 * 256);
                SL1_ACC(xv.x, row);
                SL1_ACC(xv.y, row + 16);
                SL1_ACC(xv.z, row + 32);
                SL1_ACC(xv.w, row + 48);
            }

            u64 m1 = 0ull;
            #pragma unroll
            for (int j = 0; j < 64; j++) {
                h[j] = fmaxf(h[j], 0.0f);
                if (h[j] > 0.0f) m1 |= 1ull << j;
            }

            // sign(h @ W2 + b2) via W2^T rows from smem
            u64 m2 = 0ull;
            #pragma unroll 2
            for (int j = 0; j < 64; j++) {
                const float4* wp = reinterpret_cast<const float4*>(sW2T + j * 64);
                float s0 = 0.f, s1 = 0.f, s2 = 0.f, s3 = 0.f;
                #pragma unroll
                for (int e = 0; e < 16; e++) {
                    float4 w = wp[e];
                    s0 = fmaf(w.x, h[4*e+0], s0);
                    s1 = fmaf(w.y, h[4*e+1], s1);
                    s2 = fmaf(w.z, h[4*e+2], s2);
                    s3 = fmaf(w.w, h[4*e+3], s3);
                }
                if (((s0 + s1) + (s2 + s3)) + cb2[j] > 0.0f) m2 |= 1ull << j;
            }

            // d2 into h (h dead)
            #pragma unroll
            for (int j = 0; j < 64; j++)
                h[j] = ((m2 >> j) & 1ull) ? cW3[j] : 0.0f;

            // d1_k = mask1_k * -(W2[k,:] . d2)
            float d1[64];
            #pragma unroll
            for (int k = 0; k < 64; k++) {
                const float4* wp = reinterpret_cast<const float4*>(cW2 + k * 64);
                float s0 = 0.f, s1 = 0.f, s2 = 0.f, s3 = 0.f;
                #pragma unroll
                for (int e = 0; e < 16; e++) {
                    float4 w = wp[e];
                    s0 = fmaf(w.x, h[4*e+0], s0);
                    s1 = fmaf(w.y, h[4*e+1], s1);
                    s2 = fmaf(w.z, h[4*e+2], s2);
                    s3 = fmaf(w.w, h[4*e+3], s3);
                }
                const float dk = (s0 + s1) + (s2 + s3);
                d1[k] = ((m1 >> k) & 1ull) ? -dk : 0.0f;
            }

            // out_i = W1[i,:] . d1 (negation folded above), i < 32
            float* og = out + (size_t)s * 32;
            #pragma unroll 1
            for (int i4 = 0; i4 < 8; i4++) {
                float acc[4];
                #pragma unroll
                for (int u = 0; u < 4; u++) {
                    const int i = 4 * i4 + u;
                    const float4* wp = reinterpret_cast<const float4*>(cW1 + i * 64);
                    float s0 = 0.f, s1 = 0.f, s2 = 0.f, s3 = 0.f;
                    #pragma unroll
                    for (int e = 0; e < 16; e++) {
                        float4 w = wp[e];
                        s0 = fmaf(w.x, d1[4*e+0], s0);
                        s1 = fmaf(w.y, d1[4*e+1], s1);
                        s2 = fmaf(w.z, d1[4*e+2], s2);
                        s3 = fmaf(w.w, d1[4*e+3], s3);
                    }
                    acc[u] = (s0 + s1) + (s2 + s3);
                }
                float4 r;
                r.x = acc[0]; r.y = acc[1]; r.z = acc[2]; r.w = acc[3];
                reinterpret_cast<float4*>(og)[i4] = r;
            }
        }
    }
}

extern "C" void kernel_launch(void* const* d_in, const int* in_sizes, int n_in,
                              void* d_out, int out_size)
{
    const float* X  = (const float*)d_in[0];
    const float* W1 = (const float*)d_in[1];
    const float* b1 = (const float*)d_in[2];
    const float* W2 = (const float*)d_in[3];
    const float* b2 = (const float*)d_in[4];
    const float* W3 = (const float*)d_in[5];
    float* out = (float*)d_out;

    const int B = in_sizes[0] / 64;

    cudaMemcpyToSymbolAsync(cW1, W1, 4096 * sizeof(float), 0,
                            cudaMemcpyDeviceToDevice, 0);
    cudaMemcpyToSymbolAsync(cW2, W2, 4096 * sizeof(float), 0,
                            cudaMemcpyDeviceToDevice, 0);
    cudaMemcpyToSymbolAsync(cb1, b1, 64 * sizeof(float), 0,
                            cudaMemcpyDeviceToDevice, 0);
    cudaMemcpyToSymbolAsync(cb2, b2, 64 * sizeof(float), 0,
                            cudaMemcpyDeviceToDevice, 0);
    cudaMemcpyToSymbolAsync(cW3, W3, 64 * sizeof(float), 0,
                            cudaMemcpyDeviceToDevice, 0);

    cudaFuncSetAttribute(lnn_kernel,
                         cudaFuncAttributeMaxDynamicSharedMemorySize,
                         SMEM_TOTAL);
    lnn_kernel<<<GRID, 128, SMEM_TOTAL>>>(X, W1, b1, W2, b2, W3, out, B);
}